// round 15
// baseline (speedup 1.0000x reference)
#include <cuda_runtime.h>
#include <cstdint>
#include <math_constants.h>

// Sampler: penalties + temperature + top-k/top-p mask + gumbel sample + top-L logprobs.
// One CTA per row (R14 structure — best measured, 62.0us).
//
// R15 vs R14 (instruction diet ONLY, structure unchanged):
//  * per-element max tracked in RAW logit domain (x = raw*invt, invt>0:
//    round-to-nearest is monotone, so max commutes with the scale EXACTLY);
//    one FMUL per 8-group / per chunk converts to x-domain. -1 FMUL/elem.
//  * exp arg fused: ex2(raw * (invt*log2e)) — one FMUL+MUFU instead of
//    FMUL(invt)+FMUL(log2e)+MUFU. (S shifts ~1e-7 rel: harmless at 1e-3 tol.)
//  * chunks widened to 512 elems: the serial 5-SHFL chunk reduce runs every
//    2nd iteration. Pass-2 work queue at 512-elem granularity.
// All selection logic, specials handling, sort and epilogue identical to R14.

#define NT       1024
#define SHIFT    20
#define HB       4096          // ordered-float bins: ordf(x) >> 20
#define CAND_CAP 2048
#define HASH_SZ  512
#define BM_WORDS 4096          // supports V up to 131072
#define WPT      (BM_WORDS / NT)
#define MAXCHUNK 256           // V/512 <= 256
#define BIG_NEG  (-1e30f)
#define SAMP_EPS 1e-5f
#define LOG2E    1.4426950408889634f

__device__ __forceinline__ unsigned ordf(float x) {
    unsigned u = __float_as_uint(x);
    return (u & 0x80000000u) ? ~u : (u | 0x80000000u);
}

__device__ __forceinline__ float ex2(float a) {
    float r;
    asm("ex2.approx.f32 %0, %1;" : "=f"(r) : "f"(a));
    return r;                   // ex2(-inf) = 0
}

__device__ __forceinline__ int hlookup(const int* hkey, const int* hcnt, int tok) {
    unsigned slot = ((unsigned)tok * 2654435761u) & (HASH_SZ - 1);
    while (true) {
        int k = hkey[slot];
        if (k == tok) return hcnt[slot];
        if (k == -1)  return 0;
        slot = (slot + 1) & (HASH_SZ - 1);
    }
}

// Full reference-order transform for a special (bitmap-marked) token:
// stop-min (if needed) -> repetition (if prompt/output member) -> freq/presence
// (if output member) -> temperature.
__device__ __forceinline__ float spec_val(float x, int v, bool need,
    int s0, int s1, int s2, int s3, const int* stopPenSh,
    float rp, float fp, float pp, float invt,
    const int* hkey, const int* hcnt)
{
    bool penal = true;
    if (need) {
        int which = (v == s0) ? 0 : (v == s1) ? 1 : (v == s2) ? 2 : (v == s3) ? 3 : -1;
        if (which >= 0) {
            penal = stopPenSh[which] != 0;   // was it in prompt|output?
            x = fminf(x, BIG_NEG);
        }
    }
    if (penal) {
        x = (x > 0.0f) ? (x / rp) : (x * rp);
        int c = hlookup(hkey, hcnt, v);
        if (c > 0) x -= fp * (float)c + pp;
    }
    return x * invt;
}

__global__ __launch_bounds__(NT) void sampler_kernel(
    const float* __restrict__ logits,
    const int*   __restrict__ prompt_ids,
    const int*   __restrict__ output_ids,
    const int*   __restrict__ stop_ids,
    const int*   __restrict__ min_tokens,
    const float* __restrict__ presence,
    const float* __restrict__ frequency,
    const float* __restrict__ repetition,
    const float* __restrict__ temperature,
    const int*   __restrict__ top_k,
    const float* __restrict__ top_p,
    const float* __restrict__ noise,
    float*       __restrict__ out,
    int B, int V, int P, int O, int S, int L)
{
    __shared__ unsigned bm[BM_WORDS];          // 16KB: prompt|output|(stops if need)
    __shared__ int   hkey[HASH_SZ];            // output-token count hash (4KB)
    __shared__ int   hcnt[HASH_SZ];
    __shared__ int   scratch[HB];              // 16KB, phase-overlaid:
    int*   hist  = scratch;                    //  phase 1: histogram of thread maxes
    float* candV = reinterpret_cast<float*>(scratch);   // phase 2: candidates
    int*   candI = scratch + CAND_CAP;
    __shared__ float chunkMax[MAXCHUNK];       // 1KB (512-elem chunks, x-domain)
    __shared__ int   flagged[MAXCHUNK];        // 1KB

    __shared__ float sortedV[64];
    __shared__ int   sortedI[64];
    __shared__ float scoreV[64];
    __shared__ float eV[64];
    __shared__ float redf[32];
    __shared__ int   stopPenSh[4];
    __shared__ int   shCand, shNkept, shNFlag, shQHead;
    __shared__ float shS, shLse, shTheta;

    const int b    = blockIdx.x;
    const int tid  = threadIdx.x;
    const int lane = tid & 31;
    const int wid  = tid >> 5;
    const int nChunk = V >> 9;                 // 512-elem chunks (V multiple of 512)

    // ---- init shared ----
    for (int i = tid; i < BM_WORDS; i += NT) bm[i] = 0u;
    for (int i = tid; i < HB;       i += NT) hist[i] = 0;
    for (int i = tid; i < HASH_SZ;  i += NT) { hkey[i] = -1; hcnt[i] = 0; }
    if (tid == 0) { shCand = 0; shNFlag = 0; shQHead = 0; }
    __syncthreads();

    // ---- row params ----
    const bool  need = min_tokens[b] > O;
    const float rp = repetition[b], fp = frequency[b], pp = presence[b];
    const float traw = temperature[b];
    const float t = (traw < SAMP_EPS) ? 1.0f : traw;
    const float invt = 1.0f / t;
    const float cE = invt * LOG2E;             // fused exp2 argument scale
    const int s0 = (S > 0) ? stop_ids[(size_t)b * S + 0] : -1;
    const int s1 = (S > 1) ? stop_ids[(size_t)b * S + 1] : -1;
    const int s2 = (S > 2) ? stop_ids[(size_t)b * S + 2] : -1;
    const int s3 = (S > 3) ? stop_ids[(size_t)b * S + 3] : -1;

    // ---- build membership bitmap + output counts ----
    for (int i = tid; i < O; i += NT) {
        int tok = output_ids[(size_t)b * O + i];
        atomicOr(&bm[tok >> 5], 1u << (tok & 31));
        unsigned slot = ((unsigned)tok * 2654435761u) & (HASH_SZ - 1);
        while (true) {
            int old = atomicCAS(&hkey[slot], -1, tok);
            if (old == -1 || old == tok) { atomicAdd(&hcnt[slot], 1); break; }
            slot = (slot + 1) & (HASH_SZ - 1);
        }
    }
    for (int i = tid; i < P; i += NT) {
        int tok = prompt_ids[(size_t)b * P + i];
        atomicOr(&bm[tok >> 5], 1u << (tok & 31));
    }
    __syncthreads();

    // ---- fold stop tokens into bitmap (recording prior membership) ----
    if (tid == 0 && need) {
        int ss[4] = {s0, s1, s2, s3};
        int pen[4];
        #pragma unroll
        for (int k = 0; k < 4; k++)
            pen[k] = (ss[k] >= 0) ? (int)((bm[ss[k] >> 5] >> (ss[k] & 31)) & 1u) : 0;
        #pragma unroll
        for (int k = 0; k < 4; k++) {
            stopPenSh[k] = pen[k];
            if (ss[k] >= 0) bm[ss[k] >> 5] |= 1u << (ss[k] & 31);
        }
    }
    __syncthreads();

    const float* lrow = logits + (size_t)b * V;

    // ===== PASS 1 (only full DRAM pass): raw-domain max + exp-sum + chunk maxes =====
    float mxr = -CUDART_INF_F;                  // thread max, RAW domain
    float s   = 0.0f;
    for (int ot = 0; ; ++ot) {
        const int chunk = (ot << 5) + wid;      // warp-uniform, 512-elem chunk
        const int cbase = chunk << 9;
        if (cbase >= V) break;
        float imr = -CUDART_INF_F;              // chunk max (this lane), RAW domain
        #pragma unroll
        for (int half = 0; half < 2; half++) {
            const int base = cbase + (half << 8) + (lane << 3);
            const float4 q0 = *reinterpret_cast<const float4*>(lrow + base);
            const float4 q1 = *reinterpret_cast<const float4*>(lrow + base + 4);
            const unsigned w = bm[base >> 5] >> (base & 31);   // bits 0..7

            // select raw (masked -> -inf); feeds both exp and max
            float r0 = (w &   1u) ? -CUDART_INF_F : q0.x;
            float r1 = (w &   2u) ? -CUDART_INF_F : q0.y;
            float r2 = (w &   4u) ? -CUDART_INF_F : q0.z;
            float r3 = (w &   8u) ? -CUDART_INF_F : q0.w;
            float r4 = (w &  16u) ? -CUDART_INF_F : q1.x;
            float r5 = (w &  32u) ? -CUDART_INF_F : q1.y;
            float r6 = (w &  64u) ? -CUDART_INF_F : q1.z;
            float r7 = (w & 128u) ? -CUDART_INF_F : q1.w;

            // exp2(raw * cE) == exp(raw*invt) up to one fused rounding
            float e01 = ex2(r0 * cE) + ex2(r1 * cE);
            float e23 = ex2(r2 * cE) + ex2(r3 * cE);
            float e45 = ex2(r4 * cE) + ex2(r5 * cE);
            float e67 = ex2(r6 * cE) + ex2(r7 * cE);
            s += (e01 + e23) + (e45 + e67);

            float im = fmaxf(fmaxf(fmaxf(r0, r1), fmaxf(r2, r3)),
                             fmaxf(fmaxf(r4, r5), fmaxf(r6, r7)));
            imr = fmaxf(imr, im);
        }
        mxr = fmaxf(mxr, imr);
        float cm = imr;
        #pragma unroll
        for (int o = 16; o; o >>= 1) cm = fmaxf(cm, __shfl_xor_sync(0xffffffffu, cm, o));
        if (lane == 0) chunkMax[chunk] = cm * invt;   // x-domain (max commutes with *invt)
    }
    float mx = mxr * invt;                      // thread max, x-domain (exact commute)

    // ---- specials phase A: fold transformed values into thread max + exp-sum ----
    #pragma unroll
    for (int k = 0; k < WPT; k++) {
        int wi = tid * WPT + k;
        unsigned w = bm[wi];
        int baseTok = wi << 5;
        while (w) {
            int bpos = __ffs(w) - 1; w &= (w - 1);
            int v = baseTok + bpos;
            float x = spec_val(lrow[v], v, need, s0, s1, s2, s3, stopPenSh,
                               rp, fp, pp, invt, hkey, hcnt);
            mx = fmaxf(mx, x);
            s += __expf(x);
        }
    }

    // histogram of the 1024 thread-maxes (x-domain); warp partial sums
    atomicAdd(&hist[ordf(mx) >> SHIFT], 1);
    float ws = s;
    #pragma unroll
    for (int o = 16; o; o >>= 1) ws += __shfl_xor_sync(0xffffffffu, ws, o);
    if (lane == 0) redf[wid] = ws;
    __syncthreads();                                 // hist + redf + chunkMax complete

    if (wid == 0) {                                  // final exp-sum
        float v = redf[lane];
        #pragma unroll
        for (int o = 16; o; o >>= 1) v += __shfl_xor_sync(0xffffffffu, v, o);
        if (lane == 0) shS = v;
    }
    if (wid == 1) {                                  // theta: cum-from-top >= 64
        int running = 0;
        for (int base = HB - 1; base >= 0; base -= 32) {
            int bin = base - lane;                   // lane 0 = highest bin
            int cnt = (bin >= 0) ? hist[bin] : 0;
            int pref = cnt;
            #pragma unroll
            for (int o = 1; o < 32; o <<= 1) {
                int nv = __shfl_up_sync(0xffffffffu, pref, o);
                if (lane >= o) pref += nv;
            }
            int tot = __shfl_sync(0xffffffffu, pref, 31);
            if (running + tot >= 64) {
                unsigned msk = __ballot_sync(0xffffffffu, running + pref >= 64);
                int Lm = __ffs(msk) - 1;
                int bstar = base - Lm;
                if (bstar < 0) bstar = 0;
                if (lane == 0) {
                    unsigned tu = (unsigned)bstar << SHIFT;   // bin lower edge
                    float th;
                    if (tu == 0u)               th = -CUDART_INF_F;
                    else if (tu & 0x80000000u)  th = __uint_as_float(tu ^ 0x80000000u);
                    else                        th = __uint_as_float(~tu);
                    shTheta = th;
                }
                break;
            }
            running += tot;
        }
    }
    __syncthreads();
    const float theta = shTheta;

    // ---- flag 512-elem chunks that can contain a candidate ----
    if (tid < nChunk && chunkMax[tid] >= theta) {
        int p = atomicAdd(&shNFlag, 1);
        flagged[p] = tid;
    }
    __syncthreads();
    const int nFlag = shNFlag;

    // ===== PASS 2: candidates only, flagged chunks via work queue (L2) =====
    while (true) {
        int mc;
        if (lane == 0) mc = atomicAdd(&shQHead, 1);
        mc = __shfl_sync(0xffffffffu, mc, 0);
        if (mc >= nFlag) break;
        const int c = flagged[mc];
        #pragma unroll
        for (int half = 0; half < 2; half++) {
            const int base = (c << 9) + (half << 8) + (lane << 3);
            const float4 q0 = *reinterpret_cast<const float4*>(lrow + base);
            const float4 q1 = *reinterpret_cast<const float4*>(lrow + base + 4);
            const unsigned w = bm[base >> 5] >> (base & 31);

            float x;
            #define CAND_TEST(BIT, VAL, OFF)                                   \
                if (!(w & BIT)) {                                              \
                    x = (VAL) * invt;                                          \
                    if (x >= theta) {                                          \
                        int p = atomicAdd(&shCand, 1);                         \
                        if (p < CAND_CAP) { candV[p] = x; candI[p] = base + OFF; } \
                    }                                                          \
                }
            CAND_TEST(  1u, q0.x, 0)
            CAND_TEST(  2u, q0.y, 1)
            CAND_TEST(  4u, q0.z, 2)
            CAND_TEST(  8u, q0.w, 3)
            CAND_TEST( 16u, q1.x, 4)
            CAND_TEST( 32u, q1.y, 5)
            CAND_TEST( 64u, q1.z, 6)
            CAND_TEST(128u, q1.w, 7)
            #undef CAND_TEST
        }
    }
    // specials phase B: candidate test
    #pragma unroll
    for (int k = 0; k < WPT; k++) {
        int wi = tid * WPT + k;
        unsigned w = bm[wi];
        int baseTok = wi << 5;
        while (w) {
            int bpos = __ffs(w) - 1; w &= (w - 1);
            int v = baseTok + bpos;
            float x = spec_val(lrow[v], v, need, s0, s1, s2, s3, stopPenSh,
                               rp, fp, pp, invt, hkey, hcnt);
            if (x >= theta) {
                int p = atomicAdd(&shCand, 1);
                if (p < CAND_CAP) { candV[p] = x; candI[p] = v; }
            }
        }
    }
    __syncthreads();

    // ---- exact rank sort of candidates (value desc, index asc; stable) ----
    const int C = min(shCand, CAND_CAP);
    const int Ntop = min(64, C);
    for (int i = tid; i < C; i += NT) {
        float vi = candV[i]; int ii = candI[i];
        int r = 0;
        for (int j = 0; j < C; j++) {
            float vj = candV[j];
            if (vj > vi || (vj == vi && candI[j] < ii)) r++;
        }
        if (r < 64) { sortedV[r] = vi; sortedI[r] = ii; }
    }
    __syncthreads();

    // parallel exp of top-64 (keeps expf out of the serial chain)
    if (tid < 64) eV[tid] = (tid < Ntop) ? expf(sortedV[tid]) : 0.0f;
    __syncthreads();

    // ---- prefix top-k & top-p (exclusive cumsum, strict <), masked LSE ----
    if (tid == 0) {
        const float Sall = shS;
        int ke = top_k[b]; if (ke < 1) ke = V;
        const float tp = top_p[b];
        float c = 0.0f; int nk = 0;
        for (int i = 0; i < Ntop; i++) {
            if (i < ke && c < tp) { nk = i + 1; c += eV[i] / Sall; }
            else break;
        }
        float sum = 0.0f;
        for (int i = 0; i < nk; i++) sum += eV[i];
        shLse = logf(sum);
        shNkept = nk;
    }
    __syncthreads();
    const int nk = shNkept;
    const float lse = shLse;

    // ---- gumbel scores over kept set (parallel noise gather) ----
    if (tid < nk) {
        int idx = sortedI[tid];
        float u = noise[(size_t)b * V + idx];
        float g = -logf(-logf(u));
        scoreV[tid] = sortedV[tid] * invt + g;
    }
    __syncthreads();
    if (tid == 0) {
        int best;
        if (traw < SAMP_EPS) {
            best = sortedI[0];                       // greedy: ties -> lowest index
        } else {
            best = sortedI[0]; float bs = scoreV[0];
            for (int i = 1; i < nk; i++) {
                float sc = scoreV[i]; int ix = sortedI[i];
                if (sc > bs || (sc == bs && ix < best)) { bs = sc; best = ix; }
            }
        }
        out[b] = (float)best;
    }

    // ---- top-L logprobs + indices ----
    float* lpOut = out + B + (size_t)b * L;
    float* ixOut = out + B + (size_t)B * L + (size_t)b * L;
    if (tid < L) {
        if (tid < nk) {
            lpOut[tid] = sortedV[tid] - lse;
            ixOut[tid] = (float)sortedI[tid];
        } else {
            lpOut[tid] = BIG_NEG;                    // exact: -1e30 - lse == -1e30 in f32
        }
    }
    // fill remaining index slots with the smallest non-kept token ids
    // (lax.top_k tie-break: ascending index among equal BIG_NEG values)
    const int needFill = L - nk;
    if (needFill > 0 && tid < 192) {
        int cid = tid;
        bool inKept = false; int less = 0;
        for (int i = 0; i < nk; i++) {
            int si = sortedI[i];
            inKept |= (si == cid);
            less += (si < cid);
        }
        if (!inKept) {
            int rank = cid - less;                   // rank among non-kept ids
            if (rank < needFill) ixOut[nk + rank] = (float)cid;
        }
    }
}

extern "C" void kernel_launch(void* const* d_in, const int* in_sizes, int n_in,
                              void* d_out, int out_size) {
    const float* logits  = (const float*)d_in[0];
    const int*   prompt  = (const int*)  d_in[1];
    const int*   outtok  = (const int*)  d_in[2];
    const int*   stoptok = (const int*)  d_in[3];
    const int*   mintok  = (const int*)  d_in[4];
    const float* pres    = (const float*)d_in[5];
    const float* freq    = (const float*)d_in[6];
    const float* rep     = (const float*)d_in[7];
    const float* temp    = (const float*)d_in[8];
    const int*   topk    = (const int*)  d_in[9];
    const float* topp    = (const float*)d_in[10];
    const float* noise   = (const float*)d_in[11];

    const int B = in_sizes[4];
    const int V = in_sizes[0] / B;
    const int P = in_sizes[1] / B;
    const int O = in_sizes[2] / B;
    const int S = in_sizes[3] / B;
    const int L = (out_size / B - 1) / 2;   // [sampled(B), logprobs(B,L), indices(B,L)]

    sampler_kernel<<<B, NT>>>(logits, prompt, outtok, stoptok, mintok,
                              pres, freq, rep, temp, topk, topp, noise,
                              (float*)d_out, B, V, P, O, S, L);
}

// round 16
// speedup vs baseline: 1.3398x; 1.3398x over previous
#include <cuda_runtime.h>
#include <cstdint>
#include <math_constants.h>

// Sampler: penalties + temperature + top-k/top-p mask + gumbel sample + top-L logprobs.
// One CTA per row (R15 structure; pass-1 body unchanged).
//
// R16 vs R15 — attack the serial phases (pass-1 tweaks have been null 3 rounds):
//  * specials: deterministic prefix-sum compaction of the <=2308 bitmap bits
//    into a temp list (overlaid on the unused histogram region, re-zeroed
//    after), <=3 specials per thread held in REGISTERS. Phase A batch-issues
//    independent LDGs (no serial 600-cyc-per-bit chain); phase B re-tests from
//    registers with zero loads.
//  * theta scan parallelized: 128 threads build 32-bin segment sums; warp 0
//    suffix-scans 128 segments (4 chunks) + one inner 32-bin scan. ~5x fewer
//    dependent-shfl steps.
// Everything else (pass 1 body, pass 2 queue, sort, epilogue) identical to R15.

#define NT       1024
#define SHIFT    20
#define HB       4096          // ordered-float bins: ordf(x) >> 20
#define CAND_CAP 2048
#define HASH_SZ  512
#define BM_WORDS 4096          // supports V up to 131072
#define WPT      (BM_WORDS / NT)
#define MAXCHUNK 256           // V/512 <= 256
#define NSP      3             // specials per thread (<= 2308 total < 3*1024)
#define BIG_NEG  (-1e30f)
#define SAMP_EPS 1e-5f
#define LOG2E    1.4426950408889634f

__device__ __forceinline__ unsigned ordf(float x) {
    unsigned u = __float_as_uint(x);
    return (u & 0x80000000u) ? ~u : (u | 0x80000000u);
}

__device__ __forceinline__ float ex2(float a) {
    float r;
    asm("ex2.approx.f32 %0, %1;" : "=f"(r) : "f"(a));
    return r;                   // ex2(-inf) = 0
}

__device__ __forceinline__ int hlookup(const int* hkey, const int* hcnt, int tok) {
    unsigned slot = ((unsigned)tok * 2654435761u) & (HASH_SZ - 1);
    while (true) {
        int k = hkey[slot];
        if (k == tok) return hcnt[slot];
        if (k == -1)  return 0;
        slot = (slot + 1) & (HASH_SZ - 1);
    }
}

// Full reference-order transform for a special (bitmap-marked) token:
// stop-min (if needed) -> repetition (if prompt/output member) -> freq/presence
// (if output member) -> temperature.
__device__ __forceinline__ float spec_val(float x, int v, bool need,
    int s0, int s1, int s2, int s3, const int* stopPenSh,
    float rp, float fp, float pp, float invt,
    const int* hkey, const int* hcnt)
{
    bool penal = true;
    if (need) {
        int which = (v == s0) ? 0 : (v == s1) ? 1 : (v == s2) ? 2 : (v == s3) ? 3 : -1;
        if (which >= 0) {
            penal = stopPenSh[which] != 0;   // was it in prompt|output?
            x = fminf(x, BIG_NEG);
        }
    }
    if (penal) {
        x = (x > 0.0f) ? (x / rp) : (x * rp);
        int c = hlookup(hkey, hcnt, v);
        if (c > 0) x -= fp * (float)c + pp;
    }
    return x * invt;
}

__global__ __launch_bounds__(NT) void sampler_kernel(
    const float* __restrict__ logits,
    const int*   __restrict__ prompt_ids,
    const int*   __restrict__ output_ids,
    const int*   __restrict__ stop_ids,
    const int*   __restrict__ min_tokens,
    const float* __restrict__ presence,
    const float* __restrict__ frequency,
    const float* __restrict__ repetition,
    const float* __restrict__ temperature,
    const int*   __restrict__ top_k,
    const float* __restrict__ top_p,
    const float* __restrict__ noise,
    float*       __restrict__ out,
    int B, int V, int P, int O, int S, int L)
{
    __shared__ unsigned bm[BM_WORDS];          // 16KB: prompt|output|(stops if need)
    __shared__ int   hkey[HASH_SZ];            // output-token count hash (4KB)
    __shared__ int   hcnt[HASH_SZ];
    __shared__ int   scratch[HB];              // 16KB, phase-overlaid:
    int*   hist  = scratch;                    //  (also hosts the temp specials list)
    float* candV = reinterpret_cast<float*>(scratch);   // pass 2: candidates
    int*   candI = scratch + CAND_CAP;
    __shared__ float chunkMax[MAXCHUNK];       // 1KB (512-elem chunks, x-domain)
    __shared__ int   flagged[MAXCHUNK];        // 1KB

    __shared__ float sortedV[64];
    __shared__ int   sortedI[64];
    __shared__ float scoreV[64];
    __shared__ float eV[64];
    __shared__ float redf[32];
    __shared__ int   redi[32];
    __shared__ int   seg[HB / 32];             // 128 segment sums for theta scan
    __shared__ int   stopPenSh[4];
    __shared__ int   shCand, shNkept, shNFlag, shQHead, shNSpec;
    __shared__ float shS, shLse, shTheta;

    const int b    = blockIdx.x;
    const int tid  = threadIdx.x;
    const int lane = tid & 31;
    const int wid  = tid >> 5;
    const int nChunk = V >> 9;                 // 512-elem chunks (V multiple of 512)

    // ---- init shared ----
    for (int i = tid; i < BM_WORDS; i += NT) bm[i] = 0u;
    for (int i = tid; i < HB;       i += NT) hist[i] = 0;
    for (int i = tid; i < HASH_SZ;  i += NT) { hkey[i] = -1; hcnt[i] = 0; }
    if (tid == 0) { shCand = 0; shNFlag = 0; shQHead = 0; }
    __syncthreads();

    // ---- row params ----
    const bool  need = min_tokens[b] > O;
    const float rp = repetition[b], fp = frequency[b], pp = presence[b];
    const float traw = temperature[b];
    const float t = (traw < SAMP_EPS) ? 1.0f : traw;
    const float invt = 1.0f / t;
    const float cE = invt * LOG2E;             // fused exp2 argument scale
    const int s0 = (S > 0) ? stop_ids[(size_t)b * S + 0] : -1;
    const int s1 = (S > 1) ? stop_ids[(size_t)b * S + 1] : -1;
    const int s2 = (S > 2) ? stop_ids[(size_t)b * S + 2] : -1;
    const int s3 = (S > 3) ? stop_ids[(size_t)b * S + 3] : -1;

    // ---- build membership bitmap + output counts ----
    for (int i = tid; i < O; i += NT) {
        int tok = output_ids[(size_t)b * O + i];
        atomicOr(&bm[tok >> 5], 1u << (tok & 31));
        unsigned slot = ((unsigned)tok * 2654435761u) & (HASH_SZ - 1);
        while (true) {
            int old = atomicCAS(&hkey[slot], -1, tok);
            if (old == -1 || old == tok) { atomicAdd(&hcnt[slot], 1); break; }
            slot = (slot + 1) & (HASH_SZ - 1);
        }
    }
    for (int i = tid; i < P; i += NT) {
        int tok = prompt_ids[(size_t)b * P + i];
        atomicOr(&bm[tok >> 5], 1u << (tok & 31));
    }
    __syncthreads();

    // ---- fold stop tokens into bitmap (recording prior membership) ----
    if (tid == 0 && need) {
        int ss[4] = {s0, s1, s2, s3};
        int pen[4];
        #pragma unroll
        for (int k = 0; k < 4; k++)
            pen[k] = (ss[k] >= 0) ? (int)((bm[ss[k] >> 5] >> (ss[k] & 31)) & 1u) : 0;
        #pragma unroll
        for (int k = 0; k < 4; k++) {
            stopPenSh[k] = pen[k];
            if (ss[k] >= 0) bm[ss[k] >> 5] |= 1u << (ss[k] & 31);
        }
    }
    __syncthreads();

    // ===== compact specials (deterministic prefix order) into hist region =====
    unsigned myBits[WPT];
    int tc = 0;
    #pragma unroll
    for (int k = 0; k < WPT; k++) {
        myBits[k] = bm[tid * WPT + k];
        tc += __popc(myBits[k]);
    }
    // block exclusive prefix over tc (tid order)
    int incl = tc;
    #pragma unroll
    for (int o = 1; o < 32; o <<= 1) {
        int nv = __shfl_up_sync(0xffffffffu, incl, o);
        if (lane >= o) incl += nv;
    }
    if (lane == 31) redi[wid] = incl;
    __syncthreads();
    if (wid == 0) {
        int v = redi[lane];
        int wincl = v;
        #pragma unroll
        for (int o = 1; o < 32; o <<= 1) {
            int nv = __shfl_up_sync(0xffffffffu, wincl, o);
            if (lane >= o) wincl += nv;
        }
        redi[lane] = wincl - v;                 // exclusive warp base
        if (lane == 31) shNSpec = wincl;        // block total
    }
    __syncthreads();
    int pos = redi[wid] + incl - tc;            // exclusive prefix for this thread
    #pragma unroll
    for (int k = 0; k < WPT; k++) {
        unsigned w = myBits[k];
        int baseTok = (tid * WPT + k) << 5;
        while (w) {
            int bpos = __ffs(w) - 1; w &= (w - 1);
            hist[pos++] = baseTok + bpos;       // temp list in hist region
        }
    }
    __syncthreads();
    const int nSpec = shNSpec;                  // <= P+O+4 <= 2308 < NSP*NT

    // each thread takes its <=NSP specials into registers
    int   sv[NSP];
    int   myN = 0;
    #pragma unroll
    for (int j = 0; j < NSP; j++) {
        int i = tid + j * NT;
        sv[j] = (i < nSpec) ? hist[i] : 0;
        if (i < nSpec) myN = j + 1;
    }
    __syncthreads();
    // re-zero the hist region used by the list
    for (int i = tid; i < nSpec; i += NT) hist[i] = 0;
    __syncthreads();

    const float* lrow = logits + (size_t)b * V;

    // ===== specials phase A: batched independent loads, compute once =====
    float sraw[NSP];
    #pragma unroll
    for (int j = 0; j < NSP; j++)
        sraw[j] = (j < myN) ? __ldg(lrow + sv[j]) : 0.0f;
    float sx[NSP];
    float mx = -CUDART_INF_F;                   // thread max, x-domain
    float s  = 0.0f;
    #pragma unroll
    for (int j = 0; j < NSP; j++) {
        if (j < myN) {
            sx[j] = spec_val(sraw[j], sv[j], need, s0, s1, s2, s3, stopPenSh,
                             rp, fp, pp, invt, hkey, hcnt);
            mx = fmaxf(mx, sx[j]);
            s += __expf(sx[j]);
        } else sx[j] = -CUDART_INF_F;
    }

    // ===== PASS 1 (only full DRAM pass): raw-domain max + exp-sum + chunk maxes =====
    float mxr = -CUDART_INF_F;                  // thread max over main tokens, RAW domain
    for (int ot = 0; ; ++ot) {
        const int chunk = (ot << 5) + wid;      // warp-uniform, 512-elem chunk
        const int cbase = chunk << 9;
        if (cbase >= V) break;
        float imr = -CUDART_INF_F;              // chunk max (this lane), RAW domain
        #pragma unroll
        for (int half = 0; half < 2; half++) {
            const int base = cbase + (half << 8) + (lane << 3);
            const float4 q0 = *reinterpret_cast<const float4*>(lrow + base);
            const float4 q1 = *reinterpret_cast<const float4*>(lrow + base + 4);
            const unsigned w = bm[base >> 5] >> (base & 31);   // bits 0..7

            float r0 = (w &   1u) ? -CUDART_INF_F : q0.x;
            float r1 = (w &   2u) ? -CUDART_INF_F : q0.y;
            float r2 = (w &   4u) ? -CUDART_INF_F : q0.z;
            float r3 = (w &   8u) ? -CUDART_INF_F : q0.w;
            float r4 = (w &  16u) ? -CUDART_INF_F : q1.x;
            float r5 = (w &  32u) ? -CUDART_INF_F : q1.y;
            float r6 = (w &  64u) ? -CUDART_INF_F : q1.z;
            float r7 = (w & 128u) ? -CUDART_INF_F : q1.w;

            float e01 = ex2(r0 * cE) + ex2(r1 * cE);
            float e23 = ex2(r2 * cE) + ex2(r3 * cE);
            float e45 = ex2(r4 * cE) + ex2(r5 * cE);
            float e67 = ex2(r6 * cE) + ex2(r7 * cE);
            s += (e01 + e23) + (e45 + e67);

            float im = fmaxf(fmaxf(fmaxf(r0, r1), fmaxf(r2, r3)),
                             fmaxf(fmaxf(r4, r5), fmaxf(r6, r7)));
            imr = fmaxf(imr, im);
        }
        mxr = fmaxf(mxr, imr);
        float cm = imr;
        #pragma unroll
        for (int o = 16; o; o >>= 1) cm = fmaxf(cm, __shfl_xor_sync(0xffffffffu, cm, o));
        if (lane == 0) chunkMax[chunk] = cm * invt;   // x-domain (max commutes)
    }
    mx = fmaxf(mx, mxr * invt);                 // thread max, x-domain

    // histogram of the 1024 thread-maxes (x-domain); warp partial sums
    atomicAdd(&hist[ordf(mx) >> SHIFT], 1);
    float ws = s;
    #pragma unroll
    for (int o = 16; o; o >>= 1) ws += __shfl_xor_sync(0xffffffffu, ws, o);
    if (lane == 0) redf[wid] = ws;
    __syncthreads();                                 // hist + redf + chunkMax complete

    // ---- theta: parallel segment sums, then 2-level scan in warp 0 ----
    if (tid < HB / 32) {                             // 128 threads: 32-bin segment sums
        int sum = 0;
        const int base = tid << 5;
        #pragma unroll
        for (int k = 0; k < 32; k++) sum += hist[base + k];
        seg[tid] = sum;
    }
    if (wid == 1) {                                  // final exp-sum (parallel w/ seg fill)
        float v = redf[lane];
        #pragma unroll
        for (int o = 16; o; o >>= 1) v += __shfl_xor_sync(0xffffffffu, v, o);
        if (lane == 0) shS = v;
    }
    __syncthreads();
    if (wid == 0) {                                  // crossing: cum-from-top >= 64
        int running = 0;
        int done = 0;
        for (int cb = (HB / 32 / 32) - 1; cb >= 0 && !done; cb--) {
            int sidx = (cb << 5) + (31 - lane);      // lane 0 = highest segment
            int cnt = seg[sidx];
            int pref = cnt;
            #pragma unroll
            for (int o = 1; o < 32; o <<= 1) {
                int nv = __shfl_up_sync(0xffffffffu, pref, o);
                if (lane >= o) pref += nv;
            }
            int tot = __shfl_sync(0xffffffffu, pref, 31);
            if (running + tot >= 64) {
                unsigned msk = __ballot_sync(0xffffffffu, running + pref >= 64);
                int Lm = __ffs(msk) - 1;
                int prefL = __shfl_sync(0xffffffffu, pref, Lm);
                int cntL  = __shfl_sync(0xffffffffu, cnt,  Lm);
                int sstar = (cb << 5) + (31 - Lm);
                int baseCnt = running + prefL - cntL;    // count strictly above segment
                // inner 32-bin scan within segment sstar
                int bin = (sstar << 5) + (31 - lane);    // lane 0 = highest bin
                int c2 = hist[bin];
                int p2 = c2;
                #pragma unroll
                for (int o = 1; o < 32; o <<= 1) {
                    int nv = __shfl_up_sync(0xffffffffu, p2, o);
                    if (lane >= o) p2 += nv;
                }
                unsigned msk2 = __ballot_sync(0xffffffffu, baseCnt + p2 >= 64);
                int Lm2 = __ffs(msk2) - 1;               // exists: tot covers the rest
                int bstar = (sstar << 5) + (31 - Lm2);
                if (bstar < 0) bstar = 0;
                if (lane == 0) {
                    unsigned tu = (unsigned)bstar << SHIFT;   // bin lower edge
                    float th;
                    if (tu == 0u)               th = -CUDART_INF_F;
                    else if (tu & 0x80000000u)  th = __uint_as_float(tu ^ 0x80000000u);
                    else                        th = __uint_as_float(~tu);
                    shTheta = th;
                }
                done = 1;
            }
            running += tot;
        }
    }
    __syncthreads();
    const float theta = shTheta;

    // ---- flag 512-elem chunks that can contain a candidate ----
    if (tid < nChunk && chunkMax[tid] >= theta) {
        int p = atomicAdd(&shNFlag, 1);
        flagged[p] = tid;
    }
    __syncthreads();
    const int nFlag = shNFlag;

    // ===== PASS 2: candidates only, flagged chunks via work queue (L2) =====
    while (true) {
        int mc;
        if (lane == 0) mc = atomicAdd(&shQHead, 1);
        mc = __shfl_sync(0xffffffffu, mc, 0);
        if (mc >= nFlag) break;
        const int c = flagged[mc];
        #pragma unroll
        for (int half = 0; half < 2; half++) {
            const int base = (c << 9) + (half << 8) + (lane << 3);
            const float4 q0 = *reinterpret_cast<const float4*>(lrow + base);
            const float4 q1 = *reinterpret_cast<const float4*>(lrow + base + 4);
            const unsigned w = bm[base >> 5] >> (base & 31);

            float x;
            #define CAND_TEST(BIT, VAL, OFF)                                   \
                if (!(w & BIT)) {                                              \
                    x = (VAL) * invt;                                          \
                    if (x >= theta) {                                          \
                        int p = atomicAdd(&shCand, 1);                         \
                        if (p < CAND_CAP) { candV[p] = x; candI[p] = base + OFF; } \
                    }                                                          \
                }
            CAND_TEST(  1u, q0.x, 0)
            CAND_TEST(  2u, q0.y, 1)
            CAND_TEST(  4u, q0.z, 2)
            CAND_TEST(  8u, q0.w, 3)
            CAND_TEST( 16u, q1.x, 4)
            CAND_TEST( 32u, q1.y, 5)
            CAND_TEST( 64u, q1.z, 6)
            CAND_TEST(128u, q1.w, 7)
            #undef CAND_TEST
        }
    }
    // specials phase B: candidate test straight from registers (no loads)
    #pragma unroll
    for (int j = 0; j < NSP; j++) {
        if (j < myN && sx[j] >= theta) {
            int p = atomicAdd(&shCand, 1);
            if (p < CAND_CAP) { candV[p] = sx[j]; candI[p] = sv[j]; }
        }
    }
    __syncthreads();

    // ---- exact rank sort of candidates (value desc, index asc; stable) ----
    const int C = min(shCand, CAND_CAP);
    const int Ntop = min(64, C);
    for (int i = tid; i < C; i += NT) {
        float vi = candV[i]; int ii = candI[i];
        int r = 0;
        for (int j = 0; j < C; j++) {
            float vj = candV[j];
            if (vj > vi || (vj == vi && candI[j] < ii)) r++;
        }
        if (r < 64) { sortedV[r] = vi; sortedI[r] = ii; }
    }
    __syncthreads();

    // parallel exp of top-64 (keeps expf out of the serial chain)
    if (tid < 64) eV[tid] = (tid < Ntop) ? expf(sortedV[tid]) : 0.0f;
    __syncthreads();

    // ---- prefix top-k & top-p (exclusive cumsum, strict <), masked LSE ----
    if (tid == 0) {
        const float Sall = shS;
        int ke = top_k[b]; if (ke < 1) ke = V;
        const float tp = top_p[b];
        float c = 0.0f; int nk = 0;
        for (int i = 0; i < Ntop; i++) {
            if (i < ke && c < tp) { nk = i + 1; c += eV[i] / Sall; }
            else break;
        }
        float sum = 0.0f;
        for (int i = 0; i < nk; i++) sum += eV[i];
        shLse = logf(sum);
        shNkept = nk;
    }
    __syncthreads();
    const int nk = shNkept;
    const float lse = shLse;

    // ---- gumbel scores over kept set (parallel noise gather) ----
    if (tid < nk) {
        int idx = sortedI[tid];
        float u = noise[(size_t)b * V + idx];
        float g = -logf(-logf(u));
        scoreV[tid] = sortedV[tid] * invt + g;
    }
    __syncthreads();
    if (tid == 0) {
        int best;
        if (traw < SAMP_EPS) {
            best = sortedI[0];                       // greedy: ties -> lowest index
        } else {
            best = sortedI[0]; float bs = scoreV[0];
            for (int i = 1; i < nk; i++) {
                float sc = scoreV[i]; int ix = sortedI[i];
                if (sc > bs || (sc == bs && ix < best)) { bs = sc; best = ix; }
            }
        }
        out[b] = (float)best;
    }

    // ---- top-L logprobs + indices ----
    float* lpOut = out + B + (size_t)b * L;
    float* ixOut = out + B + (size_t)B * L + (size_t)b * L;
    if (tid < L) {
        if (tid < nk) {
            lpOut[tid] = sortedV[tid] - lse;
            ixOut[tid] = (float)sortedI[tid];
        } else {
            lpOut[tid] = BIG_NEG;                    // exact: -1e30 - lse == -1e30 in f32
        }
    }
    // fill remaining index slots with the smallest non-kept token ids
    // (lax.top_k tie-break: ascending index among equal BIG_NEG values)
    const int needFill = L - nk;
    if (needFill > 0 && tid < 192) {
        int cid = tid;
        bool inKept = false; int less = 0;
        for (int i = 0; i < nk; i++) {
            int si = sortedI[i];
            inKept |= (si == cid);
            less += (si < cid);
        }
        if (!inKept) {
            int rank = cid - less;                   // rank among non-kept ids
            if (rank < needFill) ixOut[nk + rank] = (float)cid;
        }
    }
}

extern "C" void kernel_launch(void* const* d_in, const int* in_sizes, int n_in,
                              void* d_out, int out_size) {
    const float* logits  = (const float*)d_in[0];
    const int*   prompt  = (const int*)  d_in[1];
    const int*   outtok  = (const int*)  d_in[2];
    const int*   stoptok = (const int*)  d_in[3];
    const int*   mintok  = (const int*)  d_in[4];
    const float* pres    = (const float*)d_in[5];
    const float* freq    = (const float*)d_in[6];
    const float* rep     = (const float*)d_in[7];
    const float* temp    = (const float*)d_in[8];
    const int*   topk    = (const int*)  d_in[9];
    const float* topp    = (const float*)d_in[10];
    const float* noise   = (const float*)d_in[11];

    const int B = in_sizes[4];
    const int V = in_sizes[0] / B;
    const int P = in_sizes[1] / B;
    const int O = in_sizes[2] / B;
    const int S = in_sizes[3] / B;
    const int L = (out_size / B - 1) / 2;   // [sampled(B), logprobs(B,L), indices(B,L)]

    sampler_kernel<<<B, NT>>>(logits, prompt, outtok, stoptok, mintok,
                              pres, freq, rep, temp, topk, topp, noise,
                              (float*)d_out, B, V, P, O, S, L);
}